// round 3
// baseline (speedup 1.0000x reference)
#include <cuda_runtime.h>
#include <cuda_bf16.h>
#include <mma.h>

using namespace nvcuda;

#define SEQ 2048
#define HD  128
#define BM  64
#define BN  64
#define LDQ 136   // bf16 leading dim for Q/K/V smem tiles (pad vs 128)
#define LDS_ 72   // fp32 leading dim for S tile
#define LDP  72   // bf16 leading dim for P tile
#define LDO 132   // fp32 leading dim for O staging
#define NTHREADS 256

// smem layout (bytes):
//  q_hi,q_lo,k_hi,k_lo,v_hi,v_lo : 6 * BM*LDQ*2 = 6*17408 = 104448
//  s_buf : BM*LDS_*4 = 18432            -> 122880
//  p_hi  : BM*LDP*2  =  9216            -> 132096
//  p_lo  : BM*LDP*2  =  9216            -> 141312
//  l_buf : BM*4      =   256            -> 141568
#define SMEM_BYTES 141568

__device__ __forceinline__ void split_store(__nv_bfloat16* hi, __nv_bfloat16* lo,
                                            int idx, float x) {
    __nv_bfloat16 h = __float2bfloat16(x);
    hi[idx] = h;
    lo[idx] = __float2bfloat16(x - __bfloat162float(h));
}

__global__ void __launch_bounds__(NTHREADS, 1)
adaptive_attn_kernel(const float* __restrict__ q,
                     const float* __restrict__ k,
                     const float* __restrict__ v,
                     const float* __restrict__ alpha_p,
                     float* __restrict__ out) {
    extern __shared__ char smem[];
    constexpr int TILE_E = BM * LDQ;  // elements per bf16 tile

    __nv_bfloat16* q_hi = (__nv_bfloat16*)smem;
    __nv_bfloat16* q_lo = q_hi + TILE_E;
    __nv_bfloat16* k_hi = q_lo + TILE_E;
    __nv_bfloat16* k_lo = k_hi + TILE_E;
    __nv_bfloat16* v_hi = k_lo + TILE_E;
    __nv_bfloat16* v_lo = v_hi + TILE_E;
    float*         s_buf = (float*)(v_lo + TILE_E);
    __nv_bfloat16* p_hi  = (__nv_bfloat16*)(s_buf + BM * LDS_);
    __nv_bfloat16* p_lo  = p_hi + BM * LDP;
    float*         l_buf = (float*)(p_lo + BM * LDP);
    float*         o_stage = (float*)smem;   // reuse q_hi/q_lo region after mainloop

    const int tid = threadIdx.x;
    const int w   = tid >> 5;
    const int wr  = w >> 1;   // row group 0..3 (16 rows each)
    const int wc  = w & 1;    // col group 0..1

    const int qt = blockIdx.x;
    const int bh = blockIdx.y;
    const float av = alpha_p[0];   // logit scale (TEMPERATURE==1)

    const float* qg = q + ((long)bh * SEQ + (long)qt * BM) * HD;
    const float* kg = k + (long)bh * SEQ * HD;
    const float* vg = v + (long)bh * SEQ * HD;

    // ---- load Q tile once (fp32 -> bf16 hi/lo split) ----
    for (int i = tid; i < BM * (HD / 4); i += NTHREADS) {
        int r = i >> 5;
        int c = (i & 31) * 4;
        float4 x = *(const float4*)(qg + r * HD + c);
        int base = r * LDQ + c;
        split_store(q_hi, q_lo, base + 0, x.x);
        split_store(q_hi, q_lo, base + 1, x.y);
        split_store(q_hi, q_lo, base + 2, x.z);
        split_store(q_hi, q_lo, base + 3, x.w);
    }
    if (tid < BM) l_buf[tid] = 0.0f;

    wmma::fragment<wmma::accumulator, 16, 16, 16, float> o_acc[4];
#pragma unroll
    for (int j = 0; j < 4; ++j) wmma::fill_fragment(o_acc[j], 0.0f);

    for (int kt = 0; kt < SEQ / BN; ++kt) {
        // ---- load K,V tile (fp32 -> bf16 hi/lo) ----
        const float* kgt = kg + (long)kt * BN * HD;
        const float* vgt = vg + (long)kt * BN * HD;
        for (int i = tid; i < BN * (HD / 4); i += NTHREADS) {
            int r = i >> 5;
            int c = (i & 31) * 4;
            float4 xk = *(const float4*)(kgt + r * HD + c);
            float4 xv = *(const float4*)(vgt + r * HD + c);
            int base = r * LDQ + c;
            split_store(k_hi, k_lo, base + 0, xk.x);
            split_store(k_hi, k_lo, base + 1, xk.y);
            split_store(k_hi, k_lo, base + 2, xk.z);
            split_store(k_hi, k_lo, base + 3, xk.w);
            split_store(v_hi, v_lo, base + 0, xv.x);
            split_store(v_hi, v_lo, base + 1, xv.y);
            split_store(v_hi, v_lo, base + 2, xv.z);
            split_store(v_hi, v_lo, base + 3, xv.w);
        }
        __syncthreads();

        // ---- S = Q @ K^T  (bf16x3: hi*hi + hi*lo + lo*hi) ----
        {
            wmma::fragment<wmma::accumulator, 16, 16, 16, float> c0, c1;
            wmma::fill_fragment(c0, 0.0f);
            wmma::fill_fragment(c1, 0.0f);
#pragma unroll 2
            for (int k0 = 0; k0 < HD / 16; ++k0) {
                wmma::fragment<wmma::matrix_a, 16, 16, 16, __nv_bfloat16, wmma::row_major> ahi, alo;
                wmma::load_matrix_sync(ahi, q_hi + wr * 16 * LDQ + k0 * 16, LDQ);
                wmma::load_matrix_sync(alo, q_lo + wr * 16 * LDQ + k0 * 16, LDQ);

                wmma::fragment<wmma::matrix_b, 16, 16, 16, __nv_bfloat16, wmma::col_major> bhi, blo;
                int col0 = wc * 32;
                wmma::load_matrix_sync(bhi, k_hi + col0 * LDQ + k0 * 16, LDQ);
                wmma::load_matrix_sync(blo, k_lo + col0 * LDQ + k0 * 16, LDQ);
                wmma::mma_sync(c0, ahi, bhi, c0);
                wmma::mma_sync(c0, ahi, blo, c0);
                wmma::mma_sync(c0, alo, bhi, c0);

                wmma::load_matrix_sync(bhi, k_hi + (col0 + 16) * LDQ + k0 * 16, LDQ);
                wmma::load_matrix_sync(blo, k_lo + (col0 + 16) * LDQ + k0 * 16, LDQ);
                wmma::mma_sync(c1, ahi, bhi, c1);
                wmma::mma_sync(c1, ahi, blo, c1);
                wmma::mma_sync(c1, alo, bhi, c1);
            }
            wmma::store_matrix_sync(s_buf + wr * 16 * LDS_ + wc * 32, c0, LDS_, wmma::mem_row_major);
            wmma::store_matrix_sync(s_buf + wr * 16 * LDS_ + wc * 32 + 16, c1, LDS_, wmma::mem_row_major);
        }
        __syncthreads();

        // ---- P = exp(alpha * S); row sums; split to bf16 hi/lo ----
        {
            int r = tid >> 2;
            int j = tid & 3;
            const float* srow = s_buf + r * LDS_ + j * 16;
            __nv_bfloat16* ph = p_hi + r * LDP + j * 16;
            __nv_bfloat16* pl = p_lo + r * LDP + j * 16;
            float sum = 0.0f;
#pragma unroll
            for (int c = 0; c < 16; ++c) {
                float e = __expf(av * srow[c]);
                sum += e;
                __nv_bfloat16 h = __float2bfloat16(e);
                ph[c] = h;
                pl[c] = __float2bfloat16(e - __bfloat162float(h));
            }
            sum += __shfl_down_sync(0xffffffffu, sum, 1);
            sum += __shfl_down_sync(0xffffffffu, sum, 2);
            if (j == 0) l_buf[r] += sum;   // unique writer per row per iter
        }
        __syncthreads();

        // ---- O += P @ V  (bf16x3) ----
#pragma unroll 2
        for (int k0 = 0; k0 < BN / 16; ++k0) {
            wmma::fragment<wmma::matrix_a, 16, 16, 16, __nv_bfloat16, wmma::row_major> ahi, alo;
            wmma::load_matrix_sync(ahi, p_hi + wr * 16 * LDP + k0 * 16, LDP);
            wmma::load_matrix_sync(alo, p_lo + wr * 16 * LDP + k0 * 16, LDP);
#pragma unroll
            for (int j = 0; j < 4; ++j) {
                int col = wc * 64 + j * 16;
                wmma::fragment<wmma::matrix_b, 16, 16, 16, __nv_bfloat16, wmma::row_major> bhi, blo;
                wmma::load_matrix_sync(bhi, v_hi + k0 * 16 * LDQ + col, LDQ);
                wmma::load_matrix_sync(blo, v_lo + k0 * 16 * LDQ + col, LDQ);
                wmma::mma_sync(o_acc[j], ahi, bhi, o_acc[j]);
                wmma::mma_sync(o_acc[j], ahi, blo, o_acc[j]);
                wmma::mma_sync(o_acc[j], alo, bhi, o_acc[j]);
            }
        }
        __syncthreads();   // protect K/V smem before next iteration's loads
    }

    // ---- stage O to smem, divide by row sum, write out ----
#pragma unroll
    for (int j = 0; j < 4; ++j)
        wmma::store_matrix_sync(o_stage + wr * 16 * LDO + wc * 64 + j * 16,
                                o_acc[j], LDO, wmma::mem_row_major);
    __syncthreads();

    float* og = out + ((long)bh * SEQ + (long)qt * BM) * HD;
    {
        int r = tid >> 2;
        int j = tid & 3;
        float inv = 1.0f / l_buf[r];
        const float* orow = o_stage + r * LDO + j * 32;
        float* grow = og + r * HD + j * 32;
#pragma unroll
        for (int c = 0; c < 32; c += 4) {
            float4 x;
            x.x = orow[c + 0] * inv;
            x.y = orow[c + 1] * inv;
            x.z = orow[c + 2] * inv;
            x.w = orow[c + 3] * inv;
            *(float4*)(grow + c) = x;
        }
    }
}

extern "C" void kernel_launch(void* const* d_in, const int* in_sizes, int n_in,
                              void* d_out, int out_size) {
    const float* q = (const float*)d_in[0];
    const float* k = (const float*)d_in[1];
    const float* v = (const float*)d_in[2];
    const float* alpha = (const float*)d_in[3];
    float* out = (float*)d_out;

    int bh = in_sizes[0] / (SEQ * HD);   // B*H = 32

    cudaFuncSetAttribute(adaptive_attn_kernel,
                         cudaFuncAttributeMaxDynamicSharedMemorySize, SMEM_BYTES);

    dim3 grid(SEQ / BM, bh);
    dim3 block(NTHREADS);
    adaptive_attn_kernel<<<grid, block, SMEM_BYTES>>>(q, k, v, alpha, out);
}

// round 5
// speedup vs baseline: 2.2936x; 2.2936x over previous
#include <cuda_runtime.h>
#include <cuda_bf16.h>
#include <cstdint>

#define SEQ 2048
#define HD  128
#define BM  128
#define BN  64
#define NTH 256
#define ITERS (SEQ / BN)

// Four bf16 tiles per buffer (KHI, KLO, VHI, VLO), each 64 rows x 256B (swizzled),
// double buffered: 8 * 16KB = 128KB dynamic smem.
#define TILE_B 16384
#define SMEM_BYTES (8 * TILE_B)

// swizzled byte offset of element (row, d) inside a 64x128-bf16 tile
__device__ __forceinline__ uint32_t swz(int row, int d) {
    return ((uint32_t)row << 8) + ((((uint32_t)(d >> 3)) ^ (row & 7)) << 4) + (d & 7) * 2;
}

__device__ __forceinline__ uint32_t prmt_hi(float a, float b) {
    uint32_t r;
    asm("prmt.b32 %0, %1, %2, 0x7632;" : "=r"(r)
        : "r"(__float_as_uint(a)), "r"(__float_as_uint(b)));
    return r;
}
__device__ __forceinline__ uint32_t pack_lo(float a, float b) {
    float la = a - __uint_as_float(__float_as_uint(a) & 0xffff0000u);
    float lb = b - __uint_as_float(__float_as_uint(b) & 0xffff0000u);
    uint32_t r;
    asm("cvt.rn.bf16x2.f32 %0, %1, %2;" : "=r"(r) : "f"(lb), "f"(la));  // low = la
    return r;
}

__device__ __forceinline__ void mma16816(float* c, const uint32_t* a, uint32_t b0, uint32_t b1) {
    asm volatile(
        "mma.sync.aligned.m16n8k16.row.col.f32.bf16.bf16.f32 "
        "{%0,%1,%2,%3}, {%4,%5,%6,%7}, {%8,%9}, {%0,%1,%2,%3};"
        : "+f"(c[0]), "+f"(c[1]), "+f"(c[2]), "+f"(c[3])
        : "r"(a[0]), "r"(a[1]), "r"(a[2]), "r"(a[3]), "r"(b0), "r"(b1));
}
__device__ __forceinline__ void ldmx4(uint32_t* r, uint32_t addr) {
    asm volatile("ldmatrix.sync.aligned.m8n8.x4.shared.b16 {%0,%1,%2,%3}, [%4];"
                 : "=r"(r[0]), "=r"(r[1]), "=r"(r[2]), "=r"(r[3]) : "r"(addr));
}
__device__ __forceinline__ void ldmx4t(uint32_t* r, uint32_t addr) {
    asm volatile("ldmatrix.sync.aligned.m8n8.x4.trans.shared.b16 {%0,%1,%2,%3}, [%4];"
                 : "=r"(r[0]), "=r"(r[1]), "=r"(r[2]), "=r"(r[3]) : "r"(addr));
}
__device__ __forceinline__ void sts2(uint32_t addr, uint32_t x, uint32_t y) {
    asm volatile("st.shared.v2.b32 [%0], {%1, %2};" :: "r"(addr), "r"(x), "r"(y) : "memory");
}
__device__ __forceinline__ uint32_t smem_u32(const void* p) {
    uint32_t a;
    asm("{ .reg .u64 t; cvta.to.shared.u64 t, %1; cvt.u32.u64 %0, t; }" : "=r"(a) : "l"(p));
    return a;
}

// gmem fp32 [64][128] tile -> bf16 hi/lo swizzled smem tiles
__device__ __forceinline__ void load_tile(const float* __restrict__ gp,
                                          uint32_t hi_b, uint32_t lo_b, int tid) {
#pragma unroll
    for (int t = 0; t < 8; ++t) {
        int idx = tid + t * NTH;
        int r = idx >> 5;
        int d = (idx & 31) << 2;
        float4 x = *(const float4*)(gp + r * HD + d);
        uint32_t off = swz(r, d);
        sts2(hi_b + off, prmt_hi(x.x, x.y), prmt_hi(x.z, x.w));
        sts2(lo_b + off, pack_lo(x.x, x.y), pack_lo(x.z, x.w));
    }
}

__global__ void __launch_bounds__(NTH, 1)
adaptive_attn_mma(const float* __restrict__ q,
                  const float* __restrict__ k,
                  const float* __restrict__ v,
                  const float* __restrict__ alpha_p,
                  float* __restrict__ out) {
    extern __shared__ char smem[];
    const uint32_t sb = smem_u32(smem);
    const int tid = threadIdx.x;
    const int w = tid >> 5;
    const int lane = tid & 31;
    const int qq = lane & 3;                 // quad id (cols)
    const int jj = lane & 7;                 // ldmatrix row-within-tile
    const int g = lane >> 3;
    const int rowadd = jj + ((g >> 1) << 3); // ldmatrix row offset
    const int csel = g & 1;                  // ldmatrix chunk offset
    const int row0 = w * 16 + (lane >> 2);   // this thread's first output row

    const int qt = blockIdx.x;
    const int bh = blockIdx.y;
    const float av = alpha_p[0];

    const float* qg = q + ((long)bh * SEQ + (long)qt * BM) * HD;
    const float* kg = k + (long)bh * SEQ * HD;
    const float* vg = v + (long)bh * SEQ * HD;

    // ---- Q fragments (bf16 hi/lo), register-resident for all iterations ----
    uint32_t qah[8][4], qal[8][4];
#pragma unroll
    for (int kk = 0; kk < 8; ++kk)
#pragma unroll
        for (int r = 0; r < 4; ++r) {
            int qrow = row0 + (r & 1) * 8;
            int qcol = kk * 16 + qq * 2 + (r >> 1) * 8;
            float2 f = *(const float2*)(qg + qrow * HD + qcol);
            qah[kk][r] = prmt_hi(f.x, f.y);
            qal[kk][r] = pack_lo(f.x, f.y);
        }

    // ---- prologue: tile 0 into buffer 0 ----
    load_tile(kg, sb + 0 * TILE_B, sb + 1 * TILE_B, tid);
    load_tile(vg, sb + 2 * TILE_B, sb + 3 * TILE_B, tid);
    __syncthreads();

    float oacc[16][4];
#pragma unroll
    for (int i = 0; i < 16; ++i)
#pragma unroll
        for (int e = 0; e < 4; ++e) oacc[i][e] = 0.0f;
    float rs0 = 0.0f, rs1 = 0.0f;

    for (int i = 0; i < ITERS; ++i) {
        const uint32_t bufb = sb + (uint32_t)(i & 1) * (4 * TILE_B);
        const uint32_t khi = bufb, klo = bufb + TILE_B;
        const uint32_t vhi = bufb + 2 * TILE_B, vlo = bufb + 3 * TILE_B;

        // ---- S = Q K^T (bf16x3), S fragments in registers ----
        float sf[8][4];
#pragma unroll
        for (int nt = 0; nt < 8; ++nt)
#pragma unroll
            for (int e = 0; e < 4; ++e) sf[nt][e] = 0.0f;

#pragma unroll
        for (int kk = 0; kk < 8; ++kk) {
#pragma unroll
            for (int np = 0; np < 4; ++np) {
                uint32_t off = ((uint32_t)(np * 16 + rowadd) << 8)
                             + ((((kk << 1) | csel) ^ jj) << 4);
                uint32_t bh4[4], bl4[4];
                ldmx4(bh4, khi + off);
                ldmx4(bl4, klo + off);
                mma16816(sf[2 * np],     qah[kk], bh4[0], bh4[1]);
                mma16816(sf[2 * np],     qah[kk], bl4[0], bl4[1]);
                mma16816(sf[2 * np],     qal[kk], bh4[0], bh4[1]);
                mma16816(sf[2 * np + 1], qah[kk], bh4[2], bh4[3]);
                mma16816(sf[2 * np + 1], qah[kk], bl4[2], bl4[3]);
                mma16816(sf[2 * np + 1], qal[kk], bh4[2], bh4[3]);
            }
        }

        // ---- softmax numerator + repack S->P (A-operand frags), all in regs ----
        uint32_t ph[4][4], pl[4][4];
#pragma unroll
        for (int nt = 0; nt < 8; ++nt) {
            float p0 = __expf(av * sf[nt][0]);
            float p1 = __expf(av * sf[nt][1]);
            float p2 = __expf(av * sf[nt][2]);
            float p3 = __expf(av * sf[nt][3]);
            rs0 += p0 + p1;
            rs1 += p2 + p3;
            sf[nt][0] = p0; sf[nt][1] = p1; sf[nt][2] = p2; sf[nt][3] = p3;
        }
#pragma unroll
        for (int kk = 0; kk < 4; ++kk) {
            ph[kk][0] = prmt_hi(sf[2 * kk][0], sf[2 * kk][1]);
            ph[kk][1] = prmt_hi(sf[2 * kk][2], sf[2 * kk][3]);
            ph[kk][2] = prmt_hi(sf[2 * kk + 1][0], sf[2 * kk + 1][1]);
            ph[kk][3] = prmt_hi(sf[2 * kk + 1][2], sf[2 * kk + 1][3]);
            pl[kk][0] = pack_lo(sf[2 * kk][0], sf[2 * kk][1]);
            pl[kk][1] = pack_lo(sf[2 * kk][2], sf[2 * kk][3]);
            pl[kk][2] = pack_lo(sf[2 * kk + 1][0], sf[2 * kk + 1][1]);
            pl[kk][3] = pack_lo(sf[2 * kk + 1][2], sf[2 * kk + 1][3]);
        }

        // ---- O += P V (bf16x3); V fetched with ldmatrix.trans (no transpose stored) ----
#pragma unroll
        for (int kk = 0; kk < 4; ++kk) {
#pragma unroll
            for (int dp = 0; dp < 8; ++dp) {
                uint32_t off = ((uint32_t)(kk * 16 + rowadd) << 8)
                             + ((((dp << 1) | csel) ^ jj) << 4);
                uint32_t bh4[4], bl4[4];
                ldmx4t(bh4, vhi + off);
                ldmx4t(bl4, vlo + off);
                mma16816(oacc[2 * dp],     ph[kk], bh4[0], bh4[2]);
                mma16816(oacc[2 * dp],     ph[kk], bl4[0], bl4[2]);
                mma16816(oacc[2 * dp],     pl[kk], bh4[0], bh4[2]);
                mma16816(oacc[2 * dp + 1], ph[kk], bh4[1], bh4[3]);
                mma16816(oacc[2 * dp + 1], ph[kk], bl4[1], bl4[3]);
                mma16816(oacc[2 * dp + 1], pl[kk], bh4[1], bh4[3]);
            }
        }

        // ---- load next tile into the other buffer ----
        if (i < ITERS - 1) {
            const uint32_t nb = sb + (uint32_t)((i + 1) & 1) * (4 * TILE_B);
            const float* kt = kg + (long)(i + 1) * BN * HD;
            const float* vt = vg + (long)(i + 1) * BN * HD;
            load_tile(kt, nb + 0 * TILE_B, nb + 1 * TILE_B, tid);
            load_tile(vt, nb + 2 * TILE_B, nb + 3 * TILE_B, tid);
        }
        __syncthreads();
    }

    // ---- normalize + store ----
    rs0 += __shfl_xor_sync(0xffffffffu, rs0, 1);
    rs0 += __shfl_xor_sync(0xffffffffu, rs0, 2);
    rs1 += __shfl_xor_sync(0xffffffffu, rs1, 1);
    rs1 += __shfl_xor_sync(0xffffffffu, rs1, 2);
    const float inv0 = 1.0f / rs0;
    const float inv1 = 1.0f / rs1;

    float* og0 = out + ((long)bh * SEQ + (long)qt * BM + row0) * HD;
    float* og1 = og0 + 8 * HD;
#pragma unroll
    for (int dt = 0; dt < 16; ++dt) {
        int c = dt * 8 + qq * 2;
        float2 a, b;
        a.x = oacc[dt][0] * inv0; a.y = oacc[dt][1] * inv0;
        b.x = oacc[dt][2] * inv1; b.y = oacc[dt][3] * inv1;
        *(float2*)(og0 + c) = a;
        *(float2*)(og1 + c) = b;
    }
}

extern "C" void kernel_launch(void* const* d_in, const int* in_sizes, int n_in,
                              void* d_out, int out_size) {
    const float* q = (const float*)d_in[0];
    const float* k = (const float*)d_in[1];
    const float* v = (const float*)d_in[2];
    const float* alpha = (const float*)d_in[3];
    float* out = (float*)d_out;

    int bh = in_sizes[0] / (SEQ * HD);  // B*H = 32

    cudaFuncSetAttribute(adaptive_attn_mma,
                         cudaFuncAttributeMaxDynamicSharedMemorySize, SMEM_BYTES);

    dim3 grid(SEQ / BM, bh);
    adaptive_attn_mma<<<grid, NTH, SMEM_BYTES>>>(q, k, v, alpha, out);
}